// round 1
// baseline (speedup 1.0000x reference)
#include <cuda_runtime.h>
#include <cuda_bf16.h>
#include <cstdint>

// Problem constants
#define HH   256
#define WW   256
#define NP   (HH * WW)       // 65536 pixels
#define NG   1024            // gaussians
#define MM   50
#define NCH  150             // M*3 channels
#define NCHP 160             // padded channels (16 groups of 10)

#define PX_TILE 64
#define G_CHUNK 16

// Scratch (device globals; no allocation allowed)
__device__ float g_params[NG * 8];      // cx, cy, conic1, conic2, conic3, opacity, pad, pad
__device__ float g_featT[NG * NCHP];    // [n][channel] channel-major features, padded with 0

// ---------------------------------------------------------------------------
// Kernel 1: per-gaussian projection -> params
// ---------------------------------------------------------------------------
__global__ void prep_gaussians(const float* __restrict__ xyz,
                               const float* __restrict__ chol,
                               const float* __restrict__ opac) {
    int n = blockIdx.x * blockDim.x + threadIdx.x;
    if (n >= NG) return;
    float x = tanhf(xyz[2 * n + 0]);
    float y = tanhf(xyz[2 * n + 1]);
    float l1 = chol[3 * n + 0] + 0.5f;
    float l2 = chol[3 * n + 1];
    float l3 = chol[3 * n + 2] + 0.5f;
    float a = l1 * l1;
    float b = l1 * l2;
    float c = l2 * l2 + l3 * l3;
    float det = a * c - b * b;
    float c1 = c / det;
    float c2 = -b / det;
    float c3 = a / det;
    float cx = 0.5f * ((x + 1.0f) * (float)WW - 1.0f);
    float cy = 0.5f * ((y + 1.0f) * (float)HH - 1.0f);
    float* p = &g_params[n * 8];
    p[0] = cx; p[1] = cy; p[2] = c1; p[3] = c2; p[4] = c3; p[5] = opac[n];
    p[6] = 0.0f; p[7] = 0.0f;
}

// ---------------------------------------------------------------------------
// Kernel 2: features [K][M][N][3] -> channel-major [N][160] (padded zeros)
// ---------------------------------------------------------------------------
__global__ void prep_feats(const float* __restrict__ fdc,
                           const int* __restrict__ cid_p) {
    int n = blockIdx.x;      // gaussian
    int t = threadIdx.x;     // channel 0..159
    float v = 0.0f;
    if (t < NCH) {
        int m = t / 3;
        int c = t - 3 * m;
        int cid = *cid_p;
        v = fdc[(((size_t)cid * MM + m) * NG + n) * 3 + c];
    }
    g_featT[n * NCHP + t] = v;
}

// ---------------------------------------------------------------------------
// Kernel 3: fused alpha + accumulate (GEMM-like), f32x2 packed FMA
//   block = 256 threads, tile = 64 pixels x 160 channels
//   thread sub-tile = 4 px x 10 ch (5 f32x2 pairs)
// ---------------------------------------------------------------------------
__global__ __launch_bounds__(256, 2) void render(float* __restrict__ out) {
    __shared__ __align__(16) float  s_alpha[G_CHUNK][PX_TILE];
    __shared__ __align__(16) float2 s_feat[G_CHUNK][NCHP / 2];   // [g][80] f32x2 pairs

    const int tid = threadIdx.x;
    const int p0  = blockIdx.x * PX_TILE;

    const int pxg = tid & 15;   // pixel group: 4 px at pxg*4
    const int chg = tid >> 4;   // channel group: 10 ch at chg*10 (chg==15 -> padding)

    // alpha-phase mapping: 16 threads per gaussian, 4 px each
    const int ag   = tid >> 4;  // gaussian index within chunk
    const int asub = tid & 15;  // 4 pixels at asub*4

    unsigned long long acc[4][5];
#pragma unroll
    for (int i = 0; i < 4; i++)
#pragma unroll
        for (int k = 0; k < 5; k++) acc[i][k] = 0ull;

    const float2* fsrc = (const float2*)g_featT;
    const float4* pp   = (const float4*)g_params;

    for (int g0 = 0; g0 < NG; g0 += G_CHUNK) {
        // --- load feature chunk: 16 g x 80 float2 = 1280 float2, 5 per thread ---
#pragma unroll
        for (int k = 0; k < 5; k++) {
            int i = tid + k * 256;
            ((float2*)s_feat)[i] = fsrc[g0 * (NCHP / 2) + i];
        }
        // --- compute alpha chunk: 16 g x 64 px ---
        {
            float4 P0 = pp[(g0 + ag) * 2 + 0];
            float4 P1 = pp[(g0 + ag) * 2 + 1];
            float cx = P0.x, cy = P0.y, c1 = P0.z, c2 = P0.w, c3 = P1.x, op = P1.y;
#pragma unroll
            for (int j = 0; j < 4; j++) {
                int p = p0 + asub * 4 + j;
                float fx = (float)(p & (WW - 1));
                float fy = (float)(p >> 8);
                float dx = cx - fx;
                float dy = cy - fy;
                float sig = 0.5f * (c1 * dx * dx + c3 * dy * dy) + c2 * dx * dy;
                float al = fminf(0.999f, op * __expf(-sig));
                al = (sig >= 0.0f && al >= (1.0f / 255.0f)) ? al : 0.0f;
                s_alpha[ag][asub * 4 + j] = al;
            }
        }
        __syncthreads();

        // --- accumulate: per gaussian, 4 px x 5 f32x2 outer product ---
#pragma unroll
        for (int g = 0; g < G_CHUNK; g++) {
            float4 a4 = *(const float4*)&s_alpha[g][pxg * 4];
            unsigned long long ap[4];
            asm("mov.b64 %0, {%1,%1};" : "=l"(ap[0]) : "r"(__float_as_uint(a4.x)));
            asm("mov.b64 %0, {%1,%1};" : "=l"(ap[1]) : "r"(__float_as_uint(a4.y)));
            asm("mov.b64 %0, {%1,%1};" : "=l"(ap[2]) : "r"(__float_as_uint(a4.z)));
            asm("mov.b64 %0, {%1,%1};" : "=l"(ap[3]) : "r"(__float_as_uint(a4.w)));
            unsigned long long f[5];
#pragma unroll
            for (int k = 0; k < 5; k++)
                f[k] = *(const unsigned long long*)&s_feat[g][chg * 5 + k];
#pragma unroll
            for (int i = 0; i < 4; i++)
#pragma unroll
                for (int k = 0; k < 5; k++)
                    asm("fma.rn.f32x2 %0, %1, %2, %0;"
                        : "+l"(acc[i][k]) : "l"(ap[i]), "l"(f[k]));
        }
        __syncthreads();
    }

    // --- epilogue: unpack and store (chg==15 covers only padded channels) ---
    if (chg < 15) {
#pragma unroll
        for (int k = 0; k < 5; k++) {
            float lo[4], hi[4];
#pragma unroll
            for (int i = 0; i < 4; i++) {
                unsigned int l_, h_;
                asm("mov.b64 {%0,%1}, %2;" : "=r"(l_), "=r"(h_) : "l"(acc[i][k]));
                lo[i] = __uint_as_float(l_);
                hi[i] = __uint_as_float(h_);
            }
            int ch0 = chg * 10 + 2 * k;
            float4* o0 = (float4*)(out + (size_t)ch0 * NP + p0 + pxg * 4);
            float4* o1 = (float4*)(out + (size_t)(ch0 + 1) * NP + p0 + pxg * 4);
            *o0 = make_float4(lo[0], lo[1], lo[2], lo[3]);
            *o1 = make_float4(hi[0], hi[1], hi[2], hi[3]);
        }
    }
}

// ---------------------------------------------------------------------------
extern "C" void kernel_launch(void* const* d_in, const int* in_sizes, int n_in,
                              void* d_out, int out_size) {
    const float* xyz  = (const float*)d_in[0];  // [N,2]
    const float* chol = (const float*)d_in[1];  // [N,3]
    const float* opac = (const float*)d_in[2];  // [N,1]
    const float* fdc  = (const float*)d_in[3];  // [K,M,N,3]
    const int*   cid  = (const int*)d_in[4];    // scalar

    prep_gaussians<<<(NG + 255) / 256, 256>>>(xyz, chol, opac);
    prep_feats<<<NG, NCHP>>>(fdc, cid);
    render<<<NP / PX_TILE, 256>>>((float*)d_out);
}

// round 2
// speedup vs baseline: 16.3678x; 16.3678x over previous
#include <cuda_runtime.h>
#include <cuda_bf16.h>
#include <cstdint>

// Problem constants
#define HH   256
#define WW   256
#define NP   (HH * WW)       // 65536 pixels
#define NG   1024            // gaussians
#define MM   50
#define NCH  150             // M*3 channels
#define NCHF 152             // padded to 38 float4
#define TILE 16
#define NTX  (WW / TILE)     // 16
#define NTY  (HH / TILE)     // 16

// Scratch (device globals; no allocation allowed)
__device__ float g_params[NG * 8];      // cx, cy, conic1, conic2, conic3, opacity
__device__ int4  g_bbox[NG];            // x0, x1, y0, y1 (inclusive pixel bbox, conservative)
__device__ float g_featT[NG * NCHF];    // [n][channel] channel-major features, zero-padded

// ---------------------------------------------------------------------------
// Kernel 1: per-gaussian projection -> params + conservative bbox
// ---------------------------------------------------------------------------
__global__ void prep_gaussians(const float* __restrict__ xyz,
                               const float* __restrict__ chol,
                               const float* __restrict__ opac) {
    int n = blockIdx.x * blockDim.x + threadIdx.x;
    if (n >= NG) return;
    float x = tanhf(xyz[2 * n + 0]);
    float y = tanhf(xyz[2 * n + 1]);
    float l1 = chol[3 * n + 0] + 0.5f;
    float l2 = chol[3 * n + 1];
    float l3 = chol[3 * n + 2] + 0.5f;
    float a = l1 * l1;                 // Sigma_xx
    float b = l1 * l2;
    float c = l2 * l2 + l3 * l3;       // Sigma_yy
    float det = a * c - b * b;
    float c1 = c / det;
    float c2 = -b / det;
    float c3 = a / det;
    float cx = 0.5f * ((x + 1.0f) * (float)WW - 1.0f);
    float cy = 0.5f * ((y + 1.0f) * (float)HH - 1.0f);
    float op = opac[n];

    float* p = &g_params[n * 8];
    p[0] = cx; p[1] = cy; p[2] = c1; p[3] = c2; p[4] = c3; p[5] = op;
    p[6] = 0.0f; p[7] = 0.0f;

    // alpha >= 1/255  <=>  sigma <= ln(255*op) = T.  Ellipse bbox half extents:
    // hx = sqrt(2*T*Sigma_xx), hy = sqrt(2*T*Sigma_yy).  +/-1 px safety margin.
    int4 bb;
    float T = __logf(255.0f * op);
    if (T > 0.0f) {
        float hx = sqrtf(2.0f * T * a) + 1.0f;
        float hy = sqrtf(2.0f * T * c) + 1.0f;
        bb.x = max(0, (int)floorf(cx - hx) - 1);
        bb.y = min(WW - 1, (int)ceilf(cx + hx) + 1);
        bb.z = max(0, (int)floorf(cy - hy) - 1);
        bb.w = min(HH - 1, (int)ceilf(cy + hy) + 1);
    } else {
        bb.x = WW; bb.y = -1; bb.z = HH; bb.w = -1;   // empty
    }
    g_bbox[n] = bb;
}

// ---------------------------------------------------------------------------
// Kernel 2: features [K][M][N][3] -> channel-major [N][152] (zero-padded)
// ---------------------------------------------------------------------------
__global__ void prep_feats(const float* __restrict__ fdc,
                           const int* __restrict__ cid_p) {
    int n = blockIdx.x;      // gaussian
    int t = threadIdx.x;     // channel 0..151
    float v = 0.0f;
    if (t < NCH) {
        int m = t / 3;
        int c = t - 3 * m;
        int cid = *cid_p;
        v = fdc[(((size_t)cid * MM + m) * NG + n) * 3 + c];
    }
    g_featT[n * NCHF + t] = v;
}

// ---------------------------------------------------------------------------
// Kernel 3: tiled sparse render. One CTA per 16x16 tile, 1 thread per pixel.
// Deterministic in-kernel culling (ordered by gaussian index, no atomics).
// ---------------------------------------------------------------------------
__global__ __launch_bounds__(256) void render(float* __restrict__ out) {
    __shared__ unsigned s_mask[32];
    __shared__ int      s_off[32];
    __shared__ int      s_count;
    __shared__ short    s_list[NG];
    __shared__ __align__(16) float4 s_feat[16][NCHF / 4];
    __shared__ float    s_prm[16][6];

    const int tid  = threadIdx.x;
    const int lane = tid & 31;
    const int wid  = tid >> 5;
    const int tile = blockIdx.x;
    const int tx0  = (tile & (NTX - 1)) * TILE;
    const int ty0  = (tile >> 4) * TILE;

    // ---- cull: 1024 bbox-vs-tile tests, build ordered bitmask ----
#pragma unroll
    for (int j = 0; j < 4; j++) {
        int g = wid * 128 + j * 32 + lane;
        int4 bb = g_bbox[g];
        bool hit = (bb.x <= tx0 + TILE - 1) && (bb.y >= tx0) &&
                   (bb.z <= ty0 + TILE - 1) && (bb.w >= ty0);
        unsigned m = __ballot_sync(0xffffffffu, hit);
        if (lane == 0) s_mask[wid * 4 + j] = m;
    }
    __syncthreads();
    if (tid < 32) {
        int c = __popc(s_mask[tid]);
        int x = c;
#pragma unroll
        for (int d = 1; d < 32; d <<= 1) {
            int y = __shfl_up_sync(0xffffffffu, x, d);
            if (lane >= d) x += y;
        }
        s_off[tid] = x - c;
        if (tid == 31) s_count = x;
    }
    __syncthreads();
    if (tid < 32) {
        unsigned m = s_mask[tid];
        int o = s_off[tid];
        int base = tid * 32;
        while (m) {
            int b = __ffs(m) - 1;
            m &= m - 1;
            s_list[o++] = (short)(base + b);
        }
    }
    __syncthreads();
    const int count = s_count;

    const int   px = tx0 + (tid & 15);
    const int   py = ty0 + (tid >> 4);
    const float fx = (float)px;
    const float fy = (float)py;

    float4 acc[NCHF / 4];
#pragma unroll
    for (int k = 0; k < NCHF / 4; k++) acc[k] = make_float4(0.f, 0.f, 0.f, 0.f);

    // ---- main loop over culled gaussians, chunks of 16 staged in SMEM ----
    for (int c0 = 0; c0 < count; c0 += 16) {
        int nc = min(16, count - c0);
        for (int i = tid; i < nc * (NCHF / 4); i += 256) {
            int g = i / (NCHF / 4);
            int k = i - g * (NCHF / 4);
            s_feat[g][k] = ((const float4*)g_featT)[(int)s_list[c0 + g] * (NCHF / 4) + k];
        }
        if (tid < nc * 6) {
            int g = tid / 6;
            int k = tid - g * 6;
            s_prm[g][k] = g_params[(int)s_list[c0 + g] * 8 + k];
        }
        __syncthreads();

        for (int g = 0; g < nc; g++) {
            float cx = s_prm[g][0], cy = s_prm[g][1];
            float c1 = s_prm[g][2], c2 = s_prm[g][3], c3 = s_prm[g][4];
            float op = s_prm[g][5];
            float dx = cx - fx;
            float dy = cy - fy;
            float sig = 0.5f * (c1 * dx * dx + c3 * dy * dy) + c2 * dx * dy;
            float al = fminf(0.999f, op * __expf(-sig));
            al = (sig >= 0.0f && al >= (1.0f / 255.0f)) ? al : 0.0f;
            if (__ballot_sync(0xffffffffu, al > 0.0f) == 0u) continue;
#pragma unroll
            for (int k = 0; k < NCHF / 4; k++) {
                float4 f = s_feat[g][k];
                acc[k].x += al * f.x;
                acc[k].y += al * f.y;
                acc[k].z += al * f.z;
                acc[k].w += al * f.w;
            }
        }
        __syncthreads();
    }

    // ---- epilogue: 150 channel-strided coalesced stores ----
    const int pofs = py * WW + px;
    const float* accs = (const float*)acc;
#pragma unroll
    for (int c = 0; c < NCH; c++)
        out[(size_t)c * NP + pofs] = accs[c];
}

// ---------------------------------------------------------------------------
extern "C" void kernel_launch(void* const* d_in, const int* in_sizes, int n_in,
                              void* d_out, int out_size) {
    const float* xyz  = (const float*)d_in[0];  // [N,2]
    const float* chol = (const float*)d_in[1];  // [N,3]
    const float* opac = (const float*)d_in[2];  // [N,1]
    const float* fdc  = (const float*)d_in[3];  // [K,M,N,3]
    const int*   cid  = (const int*)d_in[4];    // scalar

    prep_gaussians<<<(NG + 255) / 256, 256>>>(xyz, chol, opac);
    prep_feats<<<NG, NCHF>>>(fdc, cid);
    render<<<NTX * NTY, 256>>>((float*)d_out);
}